// round 14
// baseline (speedup 1.0000x reference)
#include <cuda_runtime.h>

#define BB 16
#define CC 256
#define HH 128
#define WW 128
#define HW (HH*WW)      // 16384
#define HW4 (HW/4)      // 4096

#define GROUP 2                 // batches per pipeline stage (33.5 MB)
#define NGROUP (BB/GROUP)       // 8

#define RED_CTAS   (GROUP * (HW4 / 32))          // 256  (256 thr each)
#define APPLY_CTAS (GROUP * CC * HW4 / 1024)     // 2048 (256 thr, 4 float4/thr)
#define CONV_CTAS  (GROUP * HW / 256)            // 128

// Scratch (no allocations allowed)
__device__ float g_red [BB * 2 * HW];           // combined [B,2,H,W]
__device__ float g_gate[BB * HW];               // gate [B,H,W]

// ---------------------------------------------------------------------------
// Reduce body (R7 shape: 256 thr = 32 float4-cols x 8 chan-groups of 32).
// At fixed channel a warp reads 32 consecutive float4 = 512 B (coalesced).
// ---------------------------------------------------------------------------
__device__ __forceinline__ void reduce_body(const float* __restrict__ x,
                                            int g, int blk, int tid) {
    __shared__ float4 s_mx[8][33];
    __shared__ float4 s_sm[8][33];

    int col = tid & 31;
    int grp = tid >> 5;              // 0..7

    int brel    = blk >> 7;          // 0..GROUP-1
    int colBase = (blk & 127) * 32;
    int b       = g * GROUP + brel;

    const float4* xb = reinterpret_cast<const float4*>(x)
                       + ((size_t)b * CC + (size_t)grp * 32) * HW4 + colBase + col;

    float4 v0 = __ldg(xb);
    float4 mx = v0;
    float4 sm = v0;

    #pragma unroll 8
    for (int c = 1; c < 32; ++c) {
        float4 v = __ldg(xb + (size_t)c * HW4);
        mx.x = fmaxf(mx.x, v.x);  mx.y = fmaxf(mx.y, v.y);
        mx.z = fmaxf(mx.z, v.z);  mx.w = fmaxf(mx.w, v.w);
        sm.x += v.x;  sm.y += v.y;  sm.z += v.z;  sm.w += v.w;
    }

    s_mx[grp][col] = mx;
    s_sm[grp][col] = sm;
    __syncthreads();

    if (tid < 32) {
        float4 rmx = s_mx[0][tid];
        float4 rsm = s_sm[0][tid];
        #pragma unroll
        for (int s = 1; s < 8; ++s) {
            float4 m = s_mx[s][tid];
            float4 a = s_sm[s][tid];
            rmx.x = fmaxf(rmx.x, m.x);  rmx.y = fmaxf(rmx.y, m.y);
            rmx.z = fmaxf(rmx.z, m.z);  rmx.w = fmaxf(rmx.w, m.w);
            rsm.x += a.x;  rsm.y += a.y;  rsm.z += a.z;  rsm.w += a.w;
        }
        const float inv = 1.0f / (float)CC;
        float4* rout = reinterpret_cast<float4*>(g_red)
                       + (size_t)b * 2 * HW4 + colBase + tid;
        rout[0]   = rmx;
        rout[HW4] = make_float4(rsm.x * inv, rsm.y * inv, rsm.z * inv, rsm.w * inv);
    }
}

// ---------------------------------------------------------------------------
// Apply body: out = x * gate. x reads hit L2 (streamed by prior reduce);
// out stores are write-through (__stwt) so they never evict resident x.
// 4 float4 per thread, CTA covers 1024 consecutive float4.
// ---------------------------------------------------------------------------
__device__ __forceinline__ void apply_body(const float* __restrict__ x,
                                           float* __restrict__ out,
                                           int g, int blk, int tid) {
    size_t loc  = (size_t)blk * 1024 + tid;
    size_t base = (size_t)g * GROUP * CC * HW4 + loc;
    int hw4_0   = (int)(loc & (HW4 - 1));
    int brel    = blk >> 10;                 // 1024 CTAs per batch
    int b       = g * GROUP + brel;

    const float4* xp = reinterpret_cast<const float4*>(x) + base;
    float4*       op = reinterpret_cast<float4*>(out) + base;
    const float4* gp = reinterpret_cast<const float4*>(g_gate) + (size_t)b * HW4;

    float4 v0 = __ldcs(xp);
    float4 v1 = __ldcs(xp + 256);
    float4 v2 = __ldcs(xp + 512);
    float4 v3 = __ldcs(xp + 768);
    float4 g0 = __ldca(gp + ( hw4_0         & (HW4 - 1)));
    float4 g1 = __ldca(gp + ((hw4_0 + 256)  & (HW4 - 1)));
    float4 g2 = __ldca(gp + ((hw4_0 + 512)  & (HW4 - 1)));
    float4 g3 = __ldca(gp + ((hw4_0 + 768)  & (HW4 - 1)));

    float4 o;
    o.x = v0.x * g0.x; o.y = v0.y * g0.y; o.z = v0.z * g0.z; o.w = v0.w * g0.w;
    __stwt(op,       o);
    o.x = v1.x * g1.x; o.y = v1.y * g1.y; o.z = v1.z * g1.z; o.w = v1.w * g1.w;
    __stwt(op + 256, o);
    o.x = v2.x * g2.x; o.y = v2.y * g2.y; o.z = v2.z * g2.z; o.w = v2.w * g2.w;
    __stwt(op + 512, o);
    o.x = v3.x * g3.x; o.y = v3.y * g3.y; o.z = v3.z * g3.z; o.w = v3.w * g3.w;
    __stwt(op + 768, o);
}

// ---------------------------------------------------------------------------
// Standalone kernels (pipeline prologue / epilogue)
// ---------------------------------------------------------------------------
__global__ void __launch_bounds__(256) reduce_kernel(const float* __restrict__ x,
                                                     int g) {
    reduce_body(x, g, blockIdx.x, threadIdx.x);
}

__global__ void __launch_bounds__(256) apply_kernel(const float* __restrict__ x,
                                                    float* __restrict__ out,
                                                    int g) {
    apply_body(x, out, g, blockIdx.x, threadIdx.x);
}

// ---------------------------------------------------------------------------
// Fused: apply(ga) overlapped with reduce(gr).  Reduce blocks first so the
// read stream starts in wave 1 alongside the write stream.
// Grid = RED_CTAS + APPLY_CTAS.
// ---------------------------------------------------------------------------
__global__ void __launch_bounds__(256) fused_kernel(const float* __restrict__ x,
                                                    float* __restrict__ out,
                                                    int ga, int gr) {
    if (blockIdx.x < RED_CTAS)
        reduce_body(x, gr, blockIdx.x, threadIdx.x);
    else
        apply_body(x, out, ga, blockIdx.x - RED_CTAS, threadIdx.x);
}

// ---------------------------------------------------------------------------
// Conv 7x7 over [2,H,W] + hsigmoid -> g_gate. L2-hot, tiny.
// ---------------------------------------------------------------------------
__global__ void __launch_bounds__(256) conv_kernel(const float* __restrict__ w,
                                                   const float* __restrict__ bias,
                                                   int g) {
    __shared__ float sw[98];
    __shared__ float sb;
    if (threadIdx.x < 98) sw[threadIdx.x] = w[threadIdx.x];
    if (threadIdx.x == 0) sb = bias[0];
    __syncthreads();

    int idx = blockIdx.x * blockDim.x + threadIdx.x;   // 0 .. GROUP*HW-1
    int b   = g * GROUP + (idx >> 14);
    int hw  = idx & (HW - 1);
    int h   = hw >> 7;
    int wq  = hw & (WW - 1);

    const float* mp = g_red + (size_t)b * 2 * HW;   // max plane
    const float* ap = mp + HW;                      // avg plane

    float acc = sb;
    #pragma unroll
    for (int kh = 0; kh < 7; ++kh) {
        int hh = h + kh - 3;
        if (hh < 0 || hh >= HH) continue;
        int rowoff = hh * WW;
        #pragma unroll
        for (int kw = 0; kw < 7; ++kw) {
            int ww = wq + kw - 3;
            if (ww < 0 || ww >= WW) continue;
            int off = rowoff + ww;
            acc = fmaf(sw[kh * 7 + kw],      mp[off], acc);
            acc = fmaf(sw[49 + kh * 7 + kw], ap[off], acc);
        }
    }
    g_gate[(size_t)b * HW + hw] = __saturatef((acc + 3.0f) * (1.0f / 6.0f));
}

// ---------------------------------------------------------------------------
extern "C" void kernel_launch(void* const* d_in, const int* in_sizes, int n_in,
                              void* d_out, int out_size) {
    const float* x      = (const float*)d_in[0];   // [16,256,128,128]
    const float* conv_w = (const float*)d_in[1];   // [1,2,7,7]
    const float* conv_b = (const float*)d_in[2];   // [1]
    float* out = (float*)d_out;

    // Software pipeline: reduce(g+1) overlaps apply(g).
    reduce_kernel<<<RED_CTAS, 256>>>(x, 0);
    conv_kernel  <<<CONV_CTAS, 256>>>(conv_w, conv_b, 0);
    for (int g = 0; g < NGROUP - 1; ++g) {
        fused_kernel<<<RED_CTAS + APPLY_CTAS, 256>>>(x, out, g, g + 1);
        conv_kernel <<<CONV_CTAS, 256>>>(conv_w, conv_b, g + 1);
    }
    apply_kernel<<<APPLY_CTAS, 256>>>(x, out, NGROUP - 1);
}

// round 17
// speedup vs baseline: 1.0456x; 1.0456x over previous
#include <cuda_runtime.h>

#define BB 16
#define CC 256
#define HH 128
#define WW 128
#define HW (HH*WW)      // 16384
#define HW4 (HW/4)      // 4096

#define GROUP 2                 // batches per pipeline stage (33.5 MB)
#define NGROUP (BB/GROUP)       // 8

#define RED_CTAS   (GROUP * (HW4 / 32))          // 256  CTAs @256
#define APPLY_CTAS (GROUP * CC * HW4 / 1024)     // 2048 CTAs @256, 4 float4/thr
#define CONV_CTAS  (GROUP * HW / 256)            // 128  CTAs @256

// Scratch (no allocations allowed)
__device__ float g_red [BB * 2 * HW];           // combined [B,2,H,W]
__device__ float g_gate[BB * HW];               // gate [B,H,W]

// ---------------------------------------------------------------------------
// Reduce body (R7 shape: 256 thr = 32 float4-cols x 8 chan-groups of 32).
// At fixed channel a warp reads 32 consecutive float4 = 512 B (coalesced).
// ---------------------------------------------------------------------------
__device__ __forceinline__ void reduce_body(const float* __restrict__ x,
                                            int g, int blk, int tid) {
    __shared__ float4 s_mx[8][33];
    __shared__ float4 s_sm[8][33];

    int col = tid & 31;
    int grp = tid >> 5;              // 0..7

    int brel    = blk >> 7;          // 0..GROUP-1
    int colBase = (blk & 127) * 32;
    int b       = g * GROUP + brel;

    const float4* xb = reinterpret_cast<const float4*>(x)
                       + ((size_t)b * CC + (size_t)grp * 32) * HW4 + colBase + col;

    float4 v0 = __ldg(xb);
    float4 mx = v0;
    float4 sm = v0;

    #pragma unroll 8
    for (int c = 1; c < 32; ++c) {
        float4 v = __ldg(xb + (size_t)c * HW4);
        mx.x = fmaxf(mx.x, v.x);  mx.y = fmaxf(mx.y, v.y);
        mx.z = fmaxf(mx.z, v.z);  mx.w = fmaxf(mx.w, v.w);
        sm.x += v.x;  sm.y += v.y;  sm.z += v.z;  sm.w += v.w;
    }

    s_mx[grp][col] = mx;
    s_sm[grp][col] = sm;
    __syncthreads();

    if (tid < 32) {
        float4 rmx = s_mx[0][tid];
        float4 rsm = s_sm[0][tid];
        #pragma unroll
        for (int s = 1; s < 8; ++s) {
            float4 m = s_mx[s][tid];
            float4 a = s_sm[s][tid];
            rmx.x = fmaxf(rmx.x, m.x);  rmx.y = fmaxf(rmx.y, m.y);
            rmx.z = fmaxf(rmx.z, m.z);  rmx.w = fmaxf(rmx.w, m.w);
            rsm.x += a.x;  rsm.y += a.y;  rsm.z += a.z;  rsm.w += a.w;
        }
        const float inv = 1.0f / (float)CC;
        float4* rout = reinterpret_cast<float4*>(g_red)
                       + (size_t)b * 2 * HW4 + colBase + tid;
        rout[0]   = rmx;
        rout[HW4] = make_float4(rsm.x * inv, rsm.y * inv, rsm.z * inv, rsm.w * inv);
    }
}

// ---------------------------------------------------------------------------
// Conv body: 7x7 over [2,H,W] + hsigmoid -> g_gate. L2-hot.
// ---------------------------------------------------------------------------
__device__ __forceinline__ void conv_body(const float* __restrict__ w,
                                          const float* __restrict__ bias,
                                          int g, int blk, int tid) {
    __shared__ float sw[98];
    __shared__ float sb;
    if (tid < 98) sw[tid] = w[tid];
    if (tid == 0) sb = bias[0];
    __syncthreads();

    int idx = blk * 256 + tid;        // 0 .. GROUP*HW-1
    int b   = g * GROUP + (idx >> 14);
    int hw  = idx & (HW - 1);
    int h   = hw >> 7;
    int wq  = hw & (WW - 1);

    const float* mp = g_red + (size_t)b * 2 * HW;   // max plane
    const float* ap = mp + HW;                      // avg plane

    float acc = sb;
    #pragma unroll
    for (int kh = 0; kh < 7; ++kh) {
        int hh = h + kh - 3;
        if (hh < 0 || hh >= HH) continue;
        int rowoff = hh * WW;
        #pragma unroll
        for (int kw = 0; kw < 7; ++kw) {
            int ww = wq + kw - 3;
            if (ww < 0 || ww >= WW) continue;
            int off = rowoff + ww;
            acc = fmaf(sw[kh * 7 + kw],      mp[off], acc);
            acc = fmaf(sw[49 + kh * 7 + kw], ap[off], acc);
        }
    }
    g_gate[(size_t)b * HW + hw] = __saturatef((acc + 3.0f) * (1.0f / 6.0f));
}

// ---------------------------------------------------------------------------
// Apply body: out = x * gate. x reads hit L2 (streamed by reduce 2 launches
// ago); out stores write-through (__stwt) so they never evict resident x.
// ---------------------------------------------------------------------------
__device__ __forceinline__ void apply_body(const float* __restrict__ x,
                                           float* __restrict__ out,
                                           int g, int blk, int tid) {
    size_t loc  = (size_t)blk * 1024 + tid;
    size_t base = (size_t)g * GROUP * CC * HW4 + loc;
    int hw4_0   = (int)(loc & (HW4 - 1));
    int brel    = blk >> 10;                 // 1024 CTAs per batch
    int b       = g * GROUP + brel;

    const float4* xp = reinterpret_cast<const float4*>(x) + base;
    float4*       op = reinterpret_cast<float4*>(out) + base;
    const float4* gp = reinterpret_cast<const float4*>(g_gate) + (size_t)b * HW4;

    float4 v0 = __ldcs(xp);
    float4 v1 = __ldcs(xp + 256);
    float4 v2 = __ldcs(xp + 512);
    float4 v3 = __ldcs(xp + 768);
    float4 g0 = __ldca(gp + ( hw4_0         & (HW4 - 1)));
    float4 g1 = __ldca(gp + ((hw4_0 + 256)  & (HW4 - 1)));
    float4 g2 = __ldca(gp + ((hw4_0 + 512)  & (HW4 - 1)));
    float4 g3 = __ldca(gp + ((hw4_0 + 768)  & (HW4 - 1)));

    float4 o;
    o.x = v0.x * g0.x; o.y = v0.y * g0.y; o.z = v0.z * g0.z; o.w = v0.w * g0.w;
    __stwt(op,       o);
    o.x = v1.x * g1.x; o.y = v1.y * g1.y; o.z = v1.z * g1.z; o.w = v1.w * g1.w;
    __stwt(op + 256, o);
    o.x = v2.x * g2.x; o.y = v2.y * g2.y; o.z = v2.z * g2.z; o.w = v2.w * g2.w;
    __stwt(op + 512, o);
    o.x = v3.x * g3.x; o.y = v3.y * g3.y; o.z = v3.z * g3.z; o.w = v3.w * g3.w;
    __stwt(op + 768, o);
}

// ---------------------------------------------------------------------------
// Pipeline stage kernel: independent block ranges for conv(gc), reduce(gr),
// apply(ga). Any of gr/gc/ga may be disabled; host sizes the grid to the sum
// of enabled ranges (nc/nr passed as range widths). Order: conv, reduce, apply
// (conv is latency-bound, start it in wave 1).
// ---------------------------------------------------------------------------
__global__ void __launch_bounds__(256) stage_kernel(const float* __restrict__ x,
                                                    float* __restrict__ out,
                                                    const float* __restrict__ w,
                                                    const float* __restrict__ bias,
                                                    int gr, int gc, int ga,
                                                    int nc, int nr) {
    int blk = blockIdx.x;
    if (blk < nc) {
        conv_body(w, bias, gc, blk, threadIdx.x);
    } else if (blk < nc + nr) {
        reduce_body(x, gr, blk - nc, threadIdx.x);
    } else {
        apply_body(x, out, ga, blk - nc - nr, threadIdx.x);
    }
}

// ---------------------------------------------------------------------------
extern "C" void kernel_launch(void* const* d_in, const int* in_sizes, int n_in,
                              void* d_out, int out_size) {
    const float* x      = (const float*)d_in[0];   // [16,256,128,128]
    const float* conv_w = (const float*)d_in[1];   // [1,2,7,7]
    const float* conv_b = (const float*)d_in[2];   // [1]
    float* out = (float*)d_out;

    // 3-stage pipeline over NGROUP=8 groups:
    //   launch i executes reduce(i), conv(i-1), apply(i-2) where valid.
    for (int i = 0; i <= NGROUP + 1; ++i) {
        int gr = (i <= NGROUP - 1) ? i     : -1;
        int gc = (i >= 1 && i <= NGROUP)     ? i - 1 : -1;
        int ga = (i >= 2)                    ? i - 2 : -1;
        int nr = (gr >= 0) ? RED_CTAS   : 0;
        int nc = (gc >= 0) ? CONV_CTAS  : 0;
        int na = (ga >= 0) ? APPLY_CTAS : 0;
        stage_kernel<<<nc + nr + na, 256>>>(x, out, conv_w, conv_b,
                                            gr, gc, ga, nc, nr);
    }
}